// round 1
// baseline (speedup 1.0000x reference)
#include <cuda_runtime.h>

typedef unsigned long long U64;

// ---- packed f32x2 helpers (Blackwell FFMA2 path, PTX-only) ----
__device__ __forceinline__ U64 pk2(float x, float y) {
    U64 r; asm("mov.b64 %0, {%1, %2};" : "=l"(r) : "f"(x), "f"(y)); return r;
}
__device__ __forceinline__ float lo2(U64 v) {
    float x; asm("{ .reg .f32 hi; mov.b64 {%0, hi}, %1; }" : "=f"(x) : "l"(v)); return x;
}
__device__ __forceinline__ float hi2(U64 v) {
    float y; asm("{ .reg .f32 lo; mov.b64 {lo, %0}, %1; }" : "=f"(y) : "l"(v)); return y;
}
__device__ __forceinline__ U64 fma2(U64 a, U64 b, U64 c) {
    U64 d; asm("fma.rn.f32x2 %0, %1, %2, %3;" : "=l"(d) : "l"(a), "l"(b), "l"(c)); return d;
}

// ---- fast transcendentals (ex2/rcp/rsqrt approx: ~1 ulp, safe for 1e-3) ----
__device__ __forceinline__ float ex2f(float x) { float r; asm("ex2.approx.f32 %0, %1;" : "=f"(r) : "f"(x)); return r; }
__device__ __forceinline__ float rcpf(float x) { float r; asm("rcp.approx.f32 %0, %1;" : "=f"(r) : "f"(x)); return r; }
__device__ __forceinline__ float rsqf(float x) { float r; asm("rsqrt.approx.f32 %0, %1;" : "=f"(r) : "f"(x)); return r; }

__device__ __forceinline__ float sigm(float v) {
    // 1/(1+exp(-v)) = 1/(1+2^(-v*log2e))
    return rcpf(1.0f + ex2f(v * -1.4426950408889634f));
}
__device__ __forceinline__ float tanhx(float v) {
    // tanh(v) = 1 - 2/(2^(2v*log2e)+1)
    return fmaf(-2.0f, rcpf(1.0f + ex2f(v * 2.8853900817779268f)), 1.0f);
}

static constexpr int Tn = 1000;
static constexpr int In = 13;
static constexpr int Hn = 13;
static constexpr int Bn = 2048;
static constexpr long long OUT_ELEMS = (long long)Bn * Tn * 2 * Hn;   // 53,248,000
static constexpr long long HN_ELEMS  = 2LL * Bn * Hn;                 // 53,248

// One warp per batch row. Lanes 0-15: forward dir, lanes 16-31: backward dir.
// Within a 16-lane half, lane k (k<13) owns hidden element k: gate rows
// {k, 13+k, 26+k, 39+k} of W_ih and W_hh kept in registers as f32x2 pairs
// (i,f) and (g,o). Per step: layernorm via 16-wide xor reduction, then
// 13 broadcast+FFMA2 iterations per matrix, activations, local c/h update.
__global__ void __launch_bounds__(64, 7) bilstm_kernel(
    const float* __restrict__ x,
    const float* __restrict__ ln_w, const float* __restrict__ ln_b,
    const float* __restrict__ wih_f, const float* __restrict__ whh_f,
    const float* __restrict__ bih_f, const float* __restrict__ bhh_f,
    const float* __restrict__ wih_b, const float* __restrict__ whh_b,
    const float* __restrict__ bih_b, const float* __restrict__ bhh_b,
    float* __restrict__ out)
{
    const int lane = threadIdx.x & 31;
    const int warp = blockIdx.x * (blockDim.x >> 5) + (threadIdx.x >> 5);
    const int b    = warp;                 // 0..2047 (grid sized exactly)
    const int dir  = lane >> 4;            // 0 fwd, 1 bwd
    const int k    = lane & 15;
    const bool active = (k < Hn);
    const int kk   = active ? k : 0;       // safe index for idle lanes 13-15

    const float* Wih = dir ? wih_b : wih_f;
    const float* Whh = dir ? whh_b : whh_f;
    const float* Bih = dir ? bih_b : bih_f;
    const float* Bhh = dir ? bhh_b : bhh_f;

    const int r0 = kk, r1 = Hn + kk, r2 = 2 * Hn + kk, r3 = 3 * Hn + kk;

    // Weights in registers (104 floats = 52 f32x2)
    U64 w_ih_if[In], w_ih_go[In], w_hh_if[In], w_hh_go[In];
#pragma unroll
    for (int j = 0; j < In; ++j) {
        w_ih_if[j] = pk2(Wih[r0 * In + j], Wih[r1 * In + j]);
        w_ih_go[j] = pk2(Wih[r2 * In + j], Wih[r3 * In + j]);
        w_hh_if[j] = pk2(Whh[r0 * Hn + j], Whh[r1 * Hn + j]);
        w_hh_go[j] = pk2(Whh[r2 * Hn + j], Whh[r3 * Hn + j]);
    }
    const U64 bias_if = pk2(Bih[r0] + Bhh[r0], Bih[r1] + Bhh[r1]);
    const U64 bias_go = pk2(Bih[r2] + Bhh[r2], Bih[r3] + Bhh[r3]);
    const float lnw = ln_w[kk];
    const float lnb = ln_b[kk];

    // Streaming pointers (bwd walks T backwards)
    const float* xp = x + (long long)b * (Tn * In) + (dir ? (long long)(Tn - 1) * In : 0) + kk;
    const int dxp = dir ? -In : In;
    float* op = out + (long long)b * (Tn * 2 * Hn)
                    + (dir ? (long long)(Tn - 1) * 2 * Hn : 0) + dir * Hn + kk;
    const int dop = dir ? -(2 * Hn) : (2 * Hn);

    float h = 0.0f, c = 0.0f;
    float hcur = 0.0f;

    for (int t = 0; t < Tn; ++t) {
        const float xk = active ? __ldg(xp) : 0.0f;

        // LayerNorm stats over the 16-lane group (lanes 13-15 contribute 0)
        float s = xk, s2 = xk * xk;
#pragma unroll
        for (int m = 8; m >= 1; m >>= 1) {
            s  += __shfl_xor_sync(0xffffffffu, s,  m, 16);
            s2 += __shfl_xor_sync(0xffffffffu, s2, m, 16);
        }
        const float mu  = s * (1.0f / 13.0f);
        const float var = fmaf(-mu, mu, s2 * (1.0f / 13.0f));
        const float rs  = rsqf(var + 1e-5f);
        const float xn  = fmaf((xk - mu) * rs, lnw, lnb);

        U64 aif = bias_if, ago = bias_go;
#pragma unroll
        for (int j = 0; j < In; ++j) {
            const float xv = __shfl_sync(0xffffffffu, xn,   j, 16);
            const float hv = __shfl_sync(0xffffffffu, hcur, j, 16);
            const U64 xx = pk2(xv, xv);
            const U64 hh = pk2(hv, hv);
            aif = fma2(w_ih_if[j], xx, aif);
            ago = fma2(w_ih_go[j], xx, ago);
            aif = fma2(w_hh_if[j], hh, aif);
            ago = fma2(w_hh_go[j], hh, ago);
        }

        const float gi = sigm(lo2(aif));
        const float gf = sigm(hi2(aif));
        const float gg = tanhx(lo2(ago));
        const float go = sigm(hi2(ago));

        c = fmaf(gf, c, gi * gg);
        h = go * tanhx(c);
        hcur = h;

        if (active) *op = h;
        xp += dxp;
        op += dop;
    }

    if (active) {
        // h_n at OUT_ELEMS, c_n at OUT_ELEMS + HN_ELEMS; layout [dir][b][k]
        float* hn = out + OUT_ELEMS + (long long)dir * (Bn * Hn) + (long long)b * Hn + k;
        hn[0] = h;
        hn[HN_ELEMS] = c;
    }
}

extern "C" void kernel_launch(void* const* d_in, const int* in_sizes, int n_in,
                              void* d_out, int out_size)
{
    const float* x     = (const float*)d_in[0];
    const float* ln_w  = (const float*)d_in[1];
    const float* ln_b  = (const float*)d_in[2];
    const float* wih_f = (const float*)d_in[3];
    const float* whh_f = (const float*)d_in[4];
    const float* bih_f = (const float*)d_in[5];
    const float* bhh_f = (const float*)d_in[6];
    const float* wih_b = (const float*)d_in[7];
    const float* whh_b = (const float*)d_in[8];
    const float* bih_b = (const float*)d_in[9];
    const float* bhh_b = (const float*)d_in[10];
    float* out = (float*)d_out;

    // 2048 warps (one per batch row), 64-thread blocks -> 1024 blocks.
    // __launch_bounds__(64,7) caps regs at 146 -> 14 warps/SM -> single wave.
    bilstm_kernel<<<1024, 64>>>(x, ln_w, ln_b,
                                wih_f, whh_f, bih_f, bhh_f,
                                wih_b, whh_b, bih_b, bhh_b,
                                out);
}